// round 14
// baseline (speedup 1.0000x reference)
#include <cuda_runtime.h>
#include <cuda_bf16.h>
#include <cstdint>

// Problem constants
#define BATCH 8
#define NNODE 2048
#define DIM   256
#define MROWS (BATCH * NNODE)   // 16384
#define MTILES (MROWS / 16)     // 1024
#define KSTEPS (DIM / 16)       // 16
#define NPAIRS (DIM / 16)       // 16

// -------------------- scratch (no allocations allowed) --------------------
__device__ float g_H[(size_t)MROWS * DIM];   // 16 MB fp32
__device__ float g_s1[MROWS];
__device__ float g_s2[MROWS];
__device__ uint32_t g_mb[MROWS / 32];        // bit-packed mask (2 KB)
__device__ uint4 g_AFhi[(size_t)MTILES * KSTEPS * 32];   // 8 MB
__device__ uint4 g_AFlo[(size_t)MTILES * KSTEPS * 32];   // 8 MB
__device__ uint4 g_BFhi[NPAIRS * KSTEPS * 32];           // 128 KB
__device__ uint4 g_BFlo[NPAIRS * KSTEPS * 32];           // 128 KB

// ============================================================================
// Helpers (base sm_103 target: mma.sync; NO tcgen05)
// ============================================================================
__device__ __forceinline__ void mma_bf16(float* c, const uint32_t* a,
                                         const uint32_t* b) {
    asm volatile(
        "mma.sync.aligned.m16n8k16.row.col.f32.bf16.bf16.f32 "
        "{%0,%1,%2,%3}, {%4,%5,%6,%7}, {%8,%9}, {%0,%1,%2,%3};"
        : "+f"(c[0]), "+f"(c[1]), "+f"(c[2]), "+f"(c[3])
        : "r"(a[0]), "r"(a[1]), "r"(a[2]), "r"(a[3]), "r"(b[0]), "r"(b[1]));
}

__device__ __forceinline__ void split_pair(float e0, float e1,
                                           uint32_t& h, uint32_t& l) {
    asm("cvt.rn.bf16x2.f32 %0, %1, %2;" : "=r"(h) : "f"(e1), "f"(e0));
    __nv_bfloat162 hb = *(__nv_bfloat162*)&h;
    float r0 = e0 - __bfloat162float(hb.x);
    float r1 = e1 - __bfloat162float(hb.y);
    asm("cvt.rn.bf16x2.f32 %0, %1, %2;" : "=r"(l) : "f"(r1), "f"(r0));
}

// ============================================================================
// Kernel 0a: X -> A-fragments (canonical mma layout, split bf16 hi/lo)
// ============================================================================
__global__ void __launch_bounds__(256)
convert_xfrag(const float* __restrict__ X)
{
    const int gw   = blockIdx.x * 8 + (threadIdx.x >> 5);
    const int lane = threadIdx.x & 31;
    const int mtile = gw >> 4;
    const int ks    = gw & 15;
    const int g   = lane >> 2;
    const int tig = lane & 3;
    const int r0 = mtile * 16 + g;
    const int c0 = ks * 16 + tig * 2;

    float2 p00 = *(const float2*)(X + (size_t)r0 * DIM + c0);
    float2 p10 = *(const float2*)(X + (size_t)(r0 + 8) * DIM + c0);
    float2 p01 = *(const float2*)(X + (size_t)r0 * DIM + c0 + 8);
    float2 p11 = *(const float2*)(X + (size_t)(r0 + 8) * DIM + c0 + 8);

    uint32_t h[4], l[4];
    split_pair(p00.x, p00.y, h[0], l[0]);
    split_pair(p10.x, p10.y, h[1], l[1]);
    split_pair(p01.x, p01.y, h[2], l[2]);
    split_pair(p11.x, p11.y, h[3], l[3]);

    const size_t idx = (size_t)gw * 32 + lane;
    g_AFhi[idx] = make_uint4(h[0], h[1], h[2], h[3]);
    g_AFlo[idx] = make_uint4(l[0], l[1], l[2], l[3]);
}

// ============================================================================
// Kernel 0b: blocks [0,32): W -> B-fragments.
//            blocks [32,96): init g_s1/g_s2 (scalar, warp-computed).
//            block 96: bit-pack mask into g_mb (512 words).
// ============================================================================
__global__ void __launch_bounds__(256)
convert_wfrag(const float* __restrict__ W, const float* __restrict__ bias,
              const float* __restrict__ a1, const float* __restrict__ a2,
              const float* __restrict__ att_b, const float* __restrict__ mask)
{
    if (blockIdx.x == 96) {
        // 512 words, 2 per thread: word w covers mask[w*32 .. w*32+31]
#pragma unroll
        for (int r = 0; r < 2; r++) {
            const int wrd = threadIdx.x + r * 256;
            uint32_t bits = 0;
#pragma unroll 8
            for (int k = 0; k < 32; k++)
                if (mask[wrd * 32 + k] != 0.f) bits |= 1u << k;
            g_mb[wrd] = bits;
        }
        return;
    }
    if (blockIdx.x >= 32) {
        __shared__ float sc1, sc2;
        const int lane = threadIdx.x & 31;
        if (threadIdx.x < 32) {
            float d1 = 0.f, d2 = 0.f;
#pragma unroll
            for (int k = lane; k < DIM; k += 32) {
                float bv = __ldg(bias + k);
                d1 += bv * __ldg(a1 + k);
                d2 += bv * __ldg(a2 + k);
            }
#pragma unroll
            for (int o = 16; o; o >>= 1) {
                d1 += __shfl_xor_sync(0xffffffffu, d1, o);
                d2 += __shfl_xor_sync(0xffffffffu, d2, o);
            }
            if (lane == 0) { sc1 = d1 + att_b[0]; sc2 = d2; }
        }
        __syncthreads();
        const int row = (blockIdx.x - 32) * 256 + threadIdx.x;
        g_s1[row] = sc1;
        g_s2[row] = sc2;
        return;
    }

    const int gw   = blockIdx.x * 8 + (threadIdx.x >> 5);
    const int lane = threadIdx.x & 31;
    const int pair = gw >> 4;
    const int ks   = gw & 15;
    const int g   = lane >> 2;
    const int tig = lane & 3;
    const int n0 = pair * 16 + g;
    const int n1 = n0 + 8;
    const int k0 = ks * 16 + tig * 2;

    float2 q00 = *(const float2*)(W + (size_t)n0 * DIM + k0);
    float2 q01 = *(const float2*)(W + (size_t)n0 * DIM + k0 + 8);
    float2 q10 = *(const float2*)(W + (size_t)n1 * DIM + k0);
    float2 q11 = *(const float2*)(W + (size_t)n1 * DIM + k0 + 8);

    uint32_t h[4], l[4];
    split_pair(q00.x, q00.y, h[0], l[0]);
    split_pair(q01.x, q01.y, h[1], l[1]);
    split_pair(q10.x, q10.y, h[2], l[2]);
    split_pair(q11.x, q11.y, h[3], l[3]);

    const size_t idx = (size_t)gw * 32 + lane;
    g_BFhi[idx] = make_uint4(h[0], h[1], h[2], h[3]);
    g_BFlo[idx] = make_uint4(l[0], l[1], l[2], l[3]);
}

// ============================================================================
// Kernel 1: fragment-direct HMMA GEMM + fused s1/s2 epilogue (unchanged).
// ============================================================================
__global__ void __launch_bounds__(256, 1)
gemm_h_frag(const float* __restrict__ bias, const float* __restrict__ a1,
            const float* __restrict__ a2)
{
    const int tid  = threadIdx.x;
    const int wid  = tid >> 5;
    const int lane = tid & 31;
    const int cta_m = blockIdx.x * 128;
    const int cta_n = blockIdx.y * 128;

    const int wm = (wid & 1) * 64;
    const int wn = (wid >> 1) * 32;

    const int mt_base = (cta_m + wm) >> 4;
    const int np_base = (cta_n + wn) >> 4;

    const uint4* Ah = g_AFhi + (size_t)mt_base * 512 + lane;
    const uint4* Al = g_AFlo + (size_t)mt_base * 512 + lane;
    const uint4* Bh = g_BFhi + (size_t)np_base * 512 + lane;
    const uint4* Bl = g_BFlo + (size_t)np_base * 512 + lane;

    float acc[4][4][4];
#pragma unroll
    for (int mt = 0; mt < 4; mt++)
#pragma unroll
        for (int nt = 0; nt < 4; nt++)
#pragma unroll
            for (int c = 0; c < 4; c++) acc[mt][nt][c] = 0.f;

    uint4 cAh[4], cAl[4], cBh[2], cBl[2];
#pragma unroll
    for (int mt = 0; mt < 4; mt++) { cAh[mt] = Ah[mt * 512]; cAl[mt] = Al[mt * 512]; }
#pragma unroll
    for (int p = 0; p < 2; p++)    { cBh[p] = Bh[p * 512];   cBl[p] = Bl[p * 512]; }

#pragma unroll 1
    for (int ks = 0; ks < KSTEPS; ks++) {
        uint4 nAh[4], nAl[4], nBh[2], nBl[2];
        if (ks + 1 < KSTEPS) {
            const int o = (ks + 1) * 32;
#pragma unroll
            for (int mt = 0; mt < 4; mt++) {
                nAh[mt] = Ah[mt * 512 + o];
                nAl[mt] = Al[mt * 512 + o];
            }
#pragma unroll
            for (int p = 0; p < 2; p++) {
                nBh[p] = Bh[p * 512 + o];
                nBl[p] = Bl[p * 512 + o];
            }
        }

#pragma unroll
        for (int mt = 0; mt < 4; mt++) {
            const uint32_t* ah = (const uint32_t*)&cAh[mt];
            const uint32_t* al = (const uint32_t*)&cAl[mt];
#pragma unroll
            for (int nt = 0; nt < 4; nt++) {
                const uint32_t* qh = (const uint32_t*)&cBh[nt >> 1];
                const uint32_t* ql = (const uint32_t*)&cBl[nt >> 1];
                uint32_t bh[2] = { qh[(nt & 1) * 2], qh[(nt & 1) * 2 + 1] };
                uint32_t bl[2] = { ql[(nt & 1) * 2], ql[(nt & 1) * 2 + 1] };
                mma_bf16(acc[mt][nt], ah, bh);
                mma_bf16(acc[mt][nt], ah, bl);
                mma_bf16(acc[mt][nt], al, bh);
            }
        }

        if (ks + 1 < KSTEPS) {
#pragma unroll
            for (int mt = 0; mt < 4; mt++) { cAh[mt] = nAh[mt]; cAl[mt] = nAl[mt]; }
#pragma unroll
            for (int p = 0; p < 2; p++)    { cBh[p] = nBh[p];   cBl[p] = nBl[p]; }
        }
    }

    const int gid = lane >> 2;
    const int tig = lane & 3;

    float s1p[8], s2p[8];
#pragma unroll
    for (int e = 0; e < 8; e++) { s1p[e] = 0.f; s2p[e] = 0.f; }

#pragma unroll
    for (int nt = 0; nt < 4; nt++) {
        const int col = cta_n + wn + nt * 8 + tig * 2;
        const float2 bv  = *(const float2*)(bias + col);
        const float2 a1v = *(const float2*)(a1 + col);
        const float2 a2v = *(const float2*)(a2 + col);
#pragma unroll
        for (int mt = 0; mt < 4; mt++) {
            const int m0 = cta_m + wm + mt * 16 + gid;
            float2 v0 = make_float2(acc[mt][nt][0] + bv.x, acc[mt][nt][1] + bv.y);
            float2 v1 = make_float2(acc[mt][nt][2] + bv.x, acc[mt][nt][3] + bv.y);
            *(float2*)(g_H + (size_t)m0 * DIM + col)       = v0;
            *(float2*)(g_H + (size_t)(m0 + 8) * DIM + col) = v1;
            s1p[mt * 2 + 0] += acc[mt][nt][0] * a1v.x + acc[mt][nt][1] * a1v.y;
            s1p[mt * 2 + 1] += acc[mt][nt][2] * a1v.x + acc[mt][nt][3] * a1v.y;
            s2p[mt * 2 + 0] += acc[mt][nt][0] * a2v.x + acc[mt][nt][1] * a2v.y;
            s2p[mt * 2 + 1] += acc[mt][nt][2] * a2v.x + acc[mt][nt][3] * a2v.y;
        }
    }

#pragma unroll
    for (int e = 0; e < 8; e++) {
        s1p[e] += __shfl_xor_sync(0xffffffffu, s1p[e], 1);
        s1p[e] += __shfl_xor_sync(0xffffffffu, s1p[e], 2);
        s2p[e] += __shfl_xor_sync(0xffffffffu, s2p[e], 1);
        s2p[e] += __shfl_xor_sync(0xffffffffu, s2p[e], 2);
    }
    if (tig == 0) {
#pragma unroll
        for (int mt = 0; mt < 4; mt++) {
            const int m0 = cta_m + wm + mt * 16 + gid;
            atomicAdd(&g_s1[m0],     s1p[mt * 2 + 0]);
            atomicAdd(&g_s1[m0 + 8], s1p[mt * 2 + 1]);
            atomicAdd(&g_s2[m0],     s2p[mt * 2 + 0]);
            atomicAdd(&g_s2[m0 + 8], s2p[mt * 2 + 1]);
        }
    }
}

// ============================================================================
// Kernel 2: attention + aggregation.
// Phase A : adj flags AND bit-packed mask -> prefix compaction (j into pbuf.y)
// Phase A2: sigmoid on compacted entries; pack (w, j*DIM) into pbuf float2
// Phase B : contiguous even chunks per group; LDS.128 = 2 neighbors' (w,joff)
// ============================================================================
__global__ void __launch_bounds__(256)
attn_agg_kernel(const float* __restrict__ adj, const float* __restrict__ mask,
                float* __restrict__ out)
{
    const int i   = blockIdx.x;
    const int b   = blockIdx.y;
    const int tid = threadIdx.x;
    const int row = b * NNODE + i;

    __shared__ __align__(16) float2 pbuf[NNODE];   // 16 KB: (w, joff-bits)
    __shared__ float sred[4][DIM];                 // 4 KB
    __shared__ int   s_cnt;
    __shared__ float s_sum;

    const float mi = mask[row];
    float* orow = out + (size_t)row * DIM;
    if (mi == 0.f) {
        orow[tid] = 0.f;
        return;
    }

    if (tid == 0) { s_cnt = 0; s_sum = 0.f; }
    __syncthreads();

    const float* arow = adj + (size_t)row * NNODE;
    const float* s2b  = g_s2 + b * NNODE;
    const float  s1i  = g_s1[row];
    const int lane = tid & 31;

    // ---- Phase A: adj flags + bit-packed mask, prefix compaction ----
    float4 av[2];
#pragma unroll
    for (int u = 0; u < 2; u++)
        av[u] = *(const float4*)(arow + tid * 4 + u * 1024);

    const int mword = b * 64 + (tid >> 3);
    const int msh   = (tid & 7) * 4;
    const uint32_t nib0 = (g_mb[mword]      >> msh) & 0xF;
    const uint32_t nib1 = (g_mb[mword + 32] >> msh) & 0xF;

    unsigned flags = 0;
    {
        const float* ap = (const float*)&av[0];
#pragma unroll
        for (int e = 0; e < 4; e++)
            if (ap[e] != 0.f && ((nib0 >> e) & 1u)) flags |= 1u << e;
        const float* aq = (const float*)&av[1];
#pragma unroll
        for (int e = 0; e < 4; e++)
            if (aq[e] != 0.f && ((nib1 >> e) & 1u)) flags |= 1u << (4 + e);
    }

    const int cnt = __popc(flags);
    int inc = cnt;
#pragma unroll
    for (int o = 1; o < 32; o <<= 1) {
        int v = __shfl_up_sync(0xffffffffu, inc, o);
        if (lane >= o) inc += v;
    }
    const int wtot = __shfl_sync(0xffffffffu, inc, 31);
    int base = 0;
    if (lane == 31) base = atomicAdd(&s_cnt, wtot);
    base = __shfl_sync(0xffffffffu, base, 31);

    int pos = base + inc - cnt;
    unsigned f = flags;
    int* ip = (int*)pbuf;
    while (f) {
        int e = __ffs(f) - 1;
        f &= f - 1;
        ip[2 * pos + 1] = tid * 4 + (e >> 2) * 1024 + (e & 3);
        pos++;
    }
    __syncthreads();

    // ---- Phase A2: sigmoid on compacted entries; pack (w, j*DIM) ----
    const int n = s_cnt;
    float psum = 0.f;
    for (int t = tid; t < n; t += 256) {
        int j = ip[2 * t + 1];
        float lg = s1i + s2b[j];
        float w = __fdividef(1.f, 1.f + __expf(-lg));
        pbuf[t] = make_float2(w, __int_as_float(j << 8));   // j*DIM
        psum += w;
    }
#pragma unroll
    for (int o = 16; o; o >>= 1) psum += __shfl_xor_sync(0xffffffffu, psum, o);
    if (lane == 0 && psum != 0.f) atomicAdd(&s_sum, psum);
    __syncthreads();

    // ---- Phase B: contiguous even chunks; 2 neighbors per LDS.128 ----
    const float inv = 1.f / (s_sum + 1e-8f);
    const float* Hb = g_H + (size_t)b * NNODE * DIM;

    const int g  = tid >> 6;
    const int c4 = (tid & 63) * 4;

    const int q  = (((n + 3) >> 2) + 1) & ~1;   // even chunk size, 4q >= n
    const int lo = g * q;
    const int hi = (lo + q < n) ? (lo + q) : n;

    float4 acc = make_float4(0.f, 0.f, 0.f, 0.f);
    int k = lo;
    for (; k + 1 < hi; k += 2) {
        float4 p = *(const float4*)(pbuf + k);
        int j0 = __float_as_int(p.y);
        int j1 = __float_as_int(p.w);
        float4 h0 = *(const float4*)(Hb + j0 + c4);
        float4 h1 = *(const float4*)(Hb + j1 + c4);
        acc.x += p.x * h0.x + p.z * h1.x;
        acc.y += p.x * h0.y + p.z * h1.y;
        acc.z += p.x * h0.z + p.z * h1.z;
        acc.w += p.x * h0.w + p.z * h1.w;
    }
    if (k < hi) {
        float2 p = pbuf[k];
        int j0 = __float_as_int(p.y);
        float4 h0 = *(const float4*)(Hb + j0 + c4);
        acc.x += p.x * h0.x; acc.y += p.x * h0.y;
        acc.z += p.x * h0.z; acc.w += p.x * h0.w;
    }

    *(float4*)&sred[g][c4] = acc;
    __syncthreads();

    float r = sred[0][tid] + sred[1][tid] + sred[2][tid] + sred[3][tid];
    orow[tid] = r * inv;
}

// ============================================================================
// Launch: cx(0), cw+init+maskbits(1), gemm(2), attn(3)
// ============================================================================
extern "C" void kernel_launch(void* const* d_in, const int* in_sizes, int n_in,
                              void* d_out, int out_size)
{
    const float* x     = (const float*)d_in[0];
    const float* adj   = (const float*)d_in[1];
    const float* mask  = (const float*)d_in[2];
    const float* W     = (const float*)d_in[3];
    const float* bias  = (const float*)d_in[4];
    const float* a1    = (const float*)d_in[5];
    const float* a2    = (const float*)d_in[6];
    const float* att_b = (const float*)d_in[7];
    float* out = (float*)d_out;

    convert_xfrag<<<(MTILES * KSTEPS) / 8, 256>>>(x);
    convert_wfrag<<<97, 256>>>(W, bias, a1, a2, att_b, mask);

    dim3 g1(MROWS / 128, DIM / 128);      // (128, 2)
    gemm_h_frag<<<g1, 256>>>(bias, a1, a2);

    dim3 g3(NNODE, BATCH);                // (2048, 8)
    attn_agg_kernel<<<g3, 256>>>(adj, mask, out);
}

// round 15
// speedup vs baseline: 1.0914x; 1.0914x over previous
#include <cuda_runtime.h>
#include <cuda_bf16.h>
#include <cuda_fp16.h>
#include <cstdint>

// Problem constants
#define BATCH 8
#define NNODE 2048
#define DIM   256
#define MROWS (BATCH * NNODE)   // 16384
#define MTILES (MROWS / 16)     // 1024
#define KSTEPS (DIM / 16)       // 16
#define NPAIRS (DIM / 16)       // 16

// -------------------- scratch (no allocations allowed) --------------------
__device__ __half g_Hh[(size_t)MROWS * DIM];  // 8 MB fp16 H (gather source)
__device__ float g_s1[MROWS];
__device__ float g_s2[MROWS];
__device__ uint4 g_AFhi[(size_t)MTILES * KSTEPS * 32];   // 8 MB
__device__ uint4 g_AFlo[(size_t)MTILES * KSTEPS * 32];   // 8 MB
__device__ uint4 g_BFhi[NPAIRS * KSTEPS * 32];           // 128 KB
__device__ uint4 g_BFlo[NPAIRS * KSTEPS * 32];           // 128 KB

// ============================================================================
// Helpers (base sm_103 target: mma.sync; NO tcgen05)
// ============================================================================
__device__ __forceinline__ void mma_bf16(float* c, const uint32_t* a,
                                         const uint32_t* b) {
    asm volatile(
        "mma.sync.aligned.m16n8k16.row.col.f32.bf16.bf16.f32 "
        "{%0,%1,%2,%3}, {%4,%5,%6,%7}, {%8,%9}, {%0,%1,%2,%3};"
        : "+f"(c[0]), "+f"(c[1]), "+f"(c[2]), "+f"(c[3])
        : "r"(a[0]), "r"(a[1]), "r"(a[2]), "r"(a[3]), "r"(b[0]), "r"(b[1]));
}

__device__ __forceinline__ void split_pair(float e0, float e1,
                                           uint32_t& h, uint32_t& l) {
    asm("cvt.rn.bf16x2.f32 %0, %1, %2;" : "=r"(h) : "f"(e1), "f"(e0));
    __nv_bfloat162 hb = *(__nv_bfloat162*)&h;
    float r0 = e0 - __bfloat162float(hb.x);
    float r1 = e1 - __bfloat162float(hb.y);
    asm("cvt.rn.bf16x2.f32 %0, %1, %2;" : "=r"(l) : "f"(r1), "f"(r0));
}

// ============================================================================
// Kernel 0a: X -> A-fragments (canonical mma layout, split bf16 hi/lo)
// ============================================================================
__global__ void __launch_bounds__(256)
convert_xfrag(const float* __restrict__ X)
{
    const int gw   = blockIdx.x * 8 + (threadIdx.x >> 5);
    const int lane = threadIdx.x & 31;
    const int mtile = gw >> 4;
    const int ks    = gw & 15;
    const int g   = lane >> 2;
    const int tig = lane & 3;
    const int r0 = mtile * 16 + g;
    const int c0 = ks * 16 + tig * 2;

    float2 p00 = *(const float2*)(X + (size_t)r0 * DIM + c0);
    float2 p10 = *(const float2*)(X + (size_t)(r0 + 8) * DIM + c0);
    float2 p01 = *(const float2*)(X + (size_t)r0 * DIM + c0 + 8);
    float2 p11 = *(const float2*)(X + (size_t)(r0 + 8) * DIM + c0 + 8);

    uint32_t h[4], l[4];
    split_pair(p00.x, p00.y, h[0], l[0]);
    split_pair(p10.x, p10.y, h[1], l[1]);
    split_pair(p01.x, p01.y, h[2], l[2]);
    split_pair(p11.x, p11.y, h[3], l[3]);

    const size_t idx = (size_t)gw * 32 + lane;
    g_AFhi[idx] = make_uint4(h[0], h[1], h[2], h[3]);
    g_AFlo[idx] = make_uint4(l[0], l[1], l[2], l[3]);
}

// ============================================================================
// Kernel 0b: blocks [0,32): W -> B-fragments.
//            blocks [32,96): init g_s1/g_s2 (scalar, warp-computed, broadcast).
// ============================================================================
__global__ void __launch_bounds__(256)
convert_wfrag(const float* __restrict__ W, const float* __restrict__ bias,
              const float* __restrict__ a1, const float* __restrict__ a2,
              const float* __restrict__ att_b)
{
    if (blockIdx.x >= 32) {
        __shared__ float sc1, sc2;
        const int lane = threadIdx.x & 31;
        if (threadIdx.x < 32) {
            float d1 = 0.f, d2 = 0.f;
#pragma unroll
            for (int k = lane; k < DIM; k += 32) {
                float bv = __ldg(bias + k);
                d1 += bv * __ldg(a1 + k);
                d2 += bv * __ldg(a2 + k);
            }
#pragma unroll
            for (int o = 16; o; o >>= 1) {
                d1 += __shfl_xor_sync(0xffffffffu, d1, o);
                d2 += __shfl_xor_sync(0xffffffffu, d2, o);
            }
            if (lane == 0) { sc1 = d1 + att_b[0]; sc2 = d2; }
        }
        __syncthreads();
        const int row = (blockIdx.x - 32) * 256 + threadIdx.x;
        g_s1[row] = sc1;
        g_s2[row] = sc2;
        return;
    }

    const int gw   = blockIdx.x * 8 + (threadIdx.x >> 5);
    const int lane = threadIdx.x & 31;
    const int pair = gw >> 4;
    const int ks   = gw & 15;
    const int g   = lane >> 2;
    const int tig = lane & 3;
    const int n0 = pair * 16 + g;
    const int n1 = n0 + 8;
    const int k0 = ks * 16 + tig * 2;

    float2 q00 = *(const float2*)(W + (size_t)n0 * DIM + k0);
    float2 q01 = *(const float2*)(W + (size_t)n0 * DIM + k0 + 8);
    float2 q10 = *(const float2*)(W + (size_t)n1 * DIM + k0);
    float2 q11 = *(const float2*)(W + (size_t)n1 * DIM + k0 + 8);

    uint32_t h[4], l[4];
    split_pair(q00.x, q00.y, h[0], l[0]);
    split_pair(q01.x, q01.y, h[1], l[1]);
    split_pair(q10.x, q10.y, h[2], l[2]);
    split_pair(q11.x, q11.y, h[3], l[3]);

    const size_t idx = (size_t)gw * 32 + lane;
    g_BFhi[idx] = make_uint4(h[0], h[1], h[2], h[3]);
    g_BFlo[idx] = make_uint4(l[0], l[1], l[2], l[3]);
}

// ============================================================================
// Kernel 1: fragment-direct HMMA GEMM + fused s1/s2 epilogue.
// H stored fp16-only (halves epilogue DRAM writes; gather source).
// s1/s2 computed from fp32 accumulators (exact), bias term pre-folded.
// ============================================================================
__global__ void __launch_bounds__(256, 1)
gemm_h_frag(const float* __restrict__ bias, const float* __restrict__ a1,
            const float* __restrict__ a2)
{
    const int tid  = threadIdx.x;
    const int wid  = tid >> 5;
    const int lane = tid & 31;
    const int cta_m = blockIdx.x * 128;
    const int cta_n = blockIdx.y * 128;

    const int wm = (wid & 1) * 64;
    const int wn = (wid >> 1) * 32;

    const int mt_base = (cta_m + wm) >> 4;
    const int np_base = (cta_n + wn) >> 4;

    const uint4* Ah = g_AFhi + (size_t)mt_base * 512 + lane;
    const uint4* Al = g_AFlo + (size_t)mt_base * 512 + lane;
    const uint4* Bh = g_BFhi + (size_t)np_base * 512 + lane;
    const uint4* Bl = g_BFlo + (size_t)np_base * 512 + lane;

    float acc[4][4][4];
#pragma unroll
    for (int mt = 0; mt < 4; mt++)
#pragma unroll
        for (int nt = 0; nt < 4; nt++)
#pragma unroll
            for (int c = 0; c < 4; c++) acc[mt][nt][c] = 0.f;

    uint4 cAh[4], cAl[4], cBh[2], cBl[2];
#pragma unroll
    for (int mt = 0; mt < 4; mt++) { cAh[mt] = Ah[mt * 512]; cAl[mt] = Al[mt * 512]; }
#pragma unroll
    for (int p = 0; p < 2; p++)    { cBh[p] = Bh[p * 512];   cBl[p] = Bl[p * 512]; }

#pragma unroll 1
    for (int ks = 0; ks < KSTEPS; ks++) {
        uint4 nAh[4], nAl[4], nBh[2], nBl[2];
        if (ks + 1 < KSTEPS) {
            const int o = (ks + 1) * 32;
#pragma unroll
            for (int mt = 0; mt < 4; mt++) {
                nAh[mt] = Ah[mt * 512 + o];
                nAl[mt] = Al[mt * 512 + o];
            }
#pragma unroll
            for (int p = 0; p < 2; p++) {
                nBh[p] = Bh[p * 512 + o];
                nBl[p] = Bl[p * 512 + o];
            }
        }

#pragma unroll
        for (int mt = 0; mt < 4; mt++) {
            const uint32_t* ah = (const uint32_t*)&cAh[mt];
            const uint32_t* al = (const uint32_t*)&cAl[mt];
#pragma unroll
            for (int nt = 0; nt < 4; nt++) {
                const uint32_t* qh = (const uint32_t*)&cBh[nt >> 1];
                const uint32_t* ql = (const uint32_t*)&cBl[nt >> 1];
                uint32_t bh[2] = { qh[(nt & 1) * 2], qh[(nt & 1) * 2 + 1] };
                uint32_t bl[2] = { ql[(nt & 1) * 2], ql[(nt & 1) * 2 + 1] };
                mma_bf16(acc[mt][nt], ah, bh);
                mma_bf16(acc[mt][nt], ah, bl);
                mma_bf16(acc[mt][nt], al, bh);
            }
        }

        if (ks + 1 < KSTEPS) {
#pragma unroll
            for (int mt = 0; mt < 4; mt++) { cAh[mt] = nAh[mt]; cAl[mt] = nAl[mt]; }
#pragma unroll
            for (int p = 0; p < 2; p++)    { cBh[p] = nBh[p];   cBl[p] = nBl[p]; }
        }
    }

    const int gid = lane >> 2;
    const int tig = lane & 3;

    float s1p[8], s2p[8];
#pragma unroll
    for (int e = 0; e < 8; e++) { s1p[e] = 0.f; s2p[e] = 0.f; }

#pragma unroll
    for (int nt = 0; nt < 4; nt++) {
        const int col = cta_n + wn + nt * 8 + tig * 2;
        const float2 bv  = *(const float2*)(bias + col);
        const float2 a1v = *(const float2*)(a1 + col);
        const float2 a2v = *(const float2*)(a2 + col);
#pragma unroll
        for (int mt = 0; mt < 4; mt++) {
            const int m0 = cta_m + wm + mt * 16 + gid;
            float2 v0 = make_float2(acc[mt][nt][0] + bv.x, acc[mt][nt][1] + bv.y);
            float2 v1 = make_float2(acc[mt][nt][2] + bv.x, acc[mt][nt][3] + bv.y);
            *(__half2*)(g_Hh + (size_t)m0 * DIM + col)       = __float22half2_rn(v0);
            *(__half2*)(g_Hh + (size_t)(m0 + 8) * DIM + col) = __float22half2_rn(v1);
            s1p[mt * 2 + 0] += acc[mt][nt][0] * a1v.x + acc[mt][nt][1] * a1v.y;
            s1p[mt * 2 + 1] += acc[mt][nt][2] * a1v.x + acc[mt][nt][3] * a1v.y;
            s2p[mt * 2 + 0] += acc[mt][nt][0] * a2v.x + acc[mt][nt][1] * a2v.y;
            s2p[mt * 2 + 1] += acc[mt][nt][2] * a2v.x + acc[mt][nt][3] * a2v.y;
        }
    }

#pragma unroll
    for (int e = 0; e < 8; e++) {
        s1p[e] += __shfl_xor_sync(0xffffffffu, s1p[e], 1);
        s1p[e] += __shfl_xor_sync(0xffffffffu, s1p[e], 2);
        s2p[e] += __shfl_xor_sync(0xffffffffu, s2p[e], 1);
        s2p[e] += __shfl_xor_sync(0xffffffffu, s2p[e], 2);
    }
    if (tig == 0) {
#pragma unroll
        for (int mt = 0; mt < 4; mt++) {
            const int m0 = cta_m + wm + mt * 16 + gid;
            atomicAdd(&g_s1[m0],     s1p[mt * 2 + 0]);
            atomicAdd(&g_s1[m0 + 8], s1p[mt * 2 + 1]);
            atomicAdd(&g_s2[m0],     s2p[mt * 2 + 0]);
            atomicAdd(&g_s2[m0 + 8], s2p[mt * 2 + 1]);
        }
    }
}

// ============================================================================
// Kernel 2: attention + aggregation — R13 structure (94.2us best), with
// phase B gathering fp16 H (halves the L2 gather bytes: the measured binder).
// ============================================================================
__global__ void __launch_bounds__(256)
attn_agg_kernel(const float* __restrict__ adj, const float* __restrict__ mask,
                float* __restrict__ out)
{
    const int i   = blockIdx.x;
    const int b   = blockIdx.y;
    const int tid = threadIdx.x;
    const int row = b * NNODE + i;

    __shared__ float wbuf[NNODE];
    __shared__ int   jbuf[NNODE];
    __shared__ float sred[4][DIM];
    __shared__ int   s_cnt;
    __shared__ float s_sum;

    const float mi = mask[row];
    float* orow = out + (size_t)row * DIM;
    if (mi == 0.f) {
        orow[tid] = 0.f;
        return;
    }

    if (tid == 0) { s_cnt = 0; s_sum = 0.f; }
    __syncthreads();

    const float* arow = adj + (size_t)row * NNODE;
    const float* mrow = mask + b * NNODE;
    const float* s2b  = g_s2 + b * NNODE;
    const float  s1i  = g_s1[row];
    const int lane = tid & 31;

    // ---- Phase A: flags + single prefix-sum compaction (R13 proven) ----
    float4 av[2], mv[2];
#pragma unroll
    for (int u = 0; u < 2; u++) {
        int j0 = tid * 4 + u * 1024;
        av[u] = *(const float4*)(arow + j0);
        mv[u] = *(const float4*)(mrow + j0);
    }

    unsigned flags = 0;
#pragma unroll
    for (int u = 0; u < 2; u++) {
        const float* ap = (const float*)&av[u];
        const float* mp = (const float*)&mv[u];
#pragma unroll
        for (int e = 0; e < 4; e++)
            if (ap[e] * mp[e] != 0.f) flags |= 1u << (u * 4 + e);
    }

    const int cnt = __popc(flags);
    int inc = cnt;
#pragma unroll
    for (int o = 1; o < 32; o <<= 1) {
        int v = __shfl_up_sync(0xffffffffu, inc, o);
        if (lane >= o) inc += v;
    }
    const int wtot = __shfl_sync(0xffffffffu, inc, 31);
    int base = 0;
    if (lane == 31) base = atomicAdd(&s_cnt, wtot);
    base = __shfl_sync(0xffffffffu, base, 31);

    int pos = base + inc - cnt;
    unsigned f = flags;
    while (f) {
        int e = __ffs(f) - 1;
        f &= f - 1;
        jbuf[pos++] = tid * 4 + (e >> 2) * 1024 + (e & 3);
    }
    __syncthreads();

    // ---- Phase A2: sigmoid over compacted entries only ----
    const int n = s_cnt;
    float psum = 0.f;
    for (int t = tid; t < n; t += 256) {
        int j = jbuf[t];
        float lg = s1i + s2b[j];
        float w = __fdividef(1.f, 1.f + __expf(-lg));
        wbuf[t] = w;
        psum += w;
    }
#pragma unroll
    for (int o = 16; o; o >>= 1) psum += __shfl_xor_sync(0xffffffffu, psum, o);
    if (lane == 0 && psum != 0.f) atomicAdd(&s_sum, psum);
    __syncthreads();

    // ---- Phase B: gather fp16 H (uint2 per thread per neighbor) ----
    const float inv = 1.f / (s_sum + 1e-8f);
    const __half* Hb = g_Hh + (size_t)b * NNODE * DIM;

    const int g  = tid >> 6;
    const int c4 = (tid & 63) * 4;

    float4 acc = make_float4(0.f, 0.f, 0.f, 0.f);
    int k = g;
    for (; k + 4 < n; k += 8) {
        int   ja = jbuf[k],   jc = jbuf[k + 4];
        float wa = wbuf[k],   wc = wbuf[k + 4];
        uint2 ra = *(const uint2*)(Hb + (size_t)ja * DIM + c4);
        uint2 rc = *(const uint2*)(Hb + (size_t)jc * DIM + c4);
        float2 a0 = __half22float2(*(__half2*)&ra.x);
        float2 a1f = __half22float2(*(__half2*)&ra.y);
        float2 c0 = __half22float2(*(__half2*)&rc.x);
        float2 c1 = __half22float2(*(__half2*)&rc.y);
        acc.x += wa * a0.x  + wc * c0.x;
        acc.y += wa * a0.y  + wc * c0.y;
        acc.z += wa * a1f.x + wc * c1.x;
        acc.w += wa * a1f.y + wc * c1.y;
    }
    if (k < n) {
        int   ja = jbuf[k];
        float wa = wbuf[k];
        uint2 ra = *(const uint2*)(Hb + (size_t)ja * DIM + c4);
        float2 a0 = __half22float2(*(__half2*)&ra.x);
        float2 a1f = __half22float2(*(__half2*)&ra.y);
        acc.x += wa * a0.x;  acc.y += wa * a0.y;
        acc.z += wa * a1f.x; acc.w += wa * a1f.y;
    }

    *(float4*)&sred[g][c4] = acc;
    __syncthreads();

    float r = sred[0][tid] + sred[1][tid] + sred[2][tid] + sred[3][tid];
    orow[tid] = r * inv;
}

// ============================================================================
// Launch: cx(0), cw+init(1), gemm(2), attn(3)
// ============================================================================
extern "C" void kernel_launch(void* const* d_in, const int* in_sizes, int n_in,
                              void* d_out, int out_size)
{
    const float* x     = (const float*)d_in[0];
    const float* adj   = (const float*)d_in[1];
    const float* mask  = (const float*)d_in[2];
    const float* W     = (const float*)d_in[3];
    const float* bias  = (const float*)d_in[4];
    const float* a1    = (const float*)d_in[5];
    const float* a2    = (const float*)d_in[6];
    const float* att_b = (const float*)d_in[7];
    float* out = (float*)d_out;

    convert_xfrag<<<(MTILES * KSTEPS) / 8, 256>>>(x);
    convert_wfrag<<<96, 256>>>(W, bias, a1, a2, att_b);

    dim3 g1(MROWS / 128, DIM / 128);      // (128, 2)
    gemm_h_frag<<<g1, 256>>>(bias, a1, a2);

    dim3 g3(NNODE, BATCH);                // (2048, 8)
    attn_agg_kernel<<<g3, 256>>>(adj, mask, out);
}

// round 16
// speedup vs baseline: 1.1362x; 1.0411x over previous
#include <cuda_runtime.h>
#include <cuda_bf16.h>
#include <cuda_fp16.h>
#include <cstdint>

// Problem constants
#define BATCH 8
#define NNODE 2048
#define DIM   256
#define MROWS (BATCH * NNODE)   // 16384
#define MTILES (MROWS / 16)     // 1024
#define KSTEPS (DIM / 16)       // 16
#define NPAIRS (DIM / 16)       // 16

// -------------------- scratch (no allocations allowed) --------------------
__device__ __half g_Hh[(size_t)MROWS * DIM];  // 8 MB fp16 H (gather source)
__device__ float g_s1[MROWS];
__device__ float g_s2[MROWS];
__device__ uint4 g_AFhi[(size_t)MTILES * KSTEPS * 32];   // 8 MB
__device__ uint4 g_AFlo[(size_t)MTILES * KSTEPS * 32];   // 8 MB
__device__ uint4 g_BFhi[NPAIRS * KSTEPS * 32];           // 128 KB
__device__ uint4 g_BFlo[NPAIRS * KSTEPS * 32];           // 128 KB

// ============================================================================
// Helpers (base sm_103 target: mma.sync; NO tcgen05)
// ============================================================================
__device__ __forceinline__ void mma_bf16(float* c, const uint32_t* a,
                                         const uint32_t* b) {
    asm volatile(
        "mma.sync.aligned.m16n8k16.row.col.f32.bf16.bf16.f32 "
        "{%0,%1,%2,%3}, {%4,%5,%6,%7}, {%8,%9}, {%0,%1,%2,%3};"
        : "+f"(c[0]), "+f"(c[1]), "+f"(c[2]), "+f"(c[3])
        : "r"(a[0]), "r"(a[1]), "r"(a[2]), "r"(a[3]), "r"(b[0]), "r"(b[1]));
}

__device__ __forceinline__ void split_pair(float e0, float e1,
                                           uint32_t& h, uint32_t& l) {
    asm("cvt.rn.bf16x2.f32 %0, %1, %2;" : "=r"(h) : "f"(e1), "f"(e0));
    __nv_bfloat162 hb = *(__nv_bfloat162*)&h;
    float r0 = e0 - __bfloat162float(hb.x);
    float r1 = e1 - __bfloat162float(hb.y);
    asm("cvt.rn.bf16x2.f32 %0, %1, %2;" : "=r"(l) : "f"(r1), "f"(r0));
}

// ============================================================================
// Kernel 0a: X -> A-fragments (canonical mma layout, split bf16 hi/lo)
// ============================================================================
__global__ void __launch_bounds__(256)
convert_xfrag(const float* __restrict__ X)
{
    const int gw   = blockIdx.x * 8 + (threadIdx.x >> 5);
    const int lane = threadIdx.x & 31;
    const int mtile = gw >> 4;
    const int ks    = gw & 15;
    const int g   = lane >> 2;
    const int tig = lane & 3;
    const int r0 = mtile * 16 + g;
    const int c0 = ks * 16 + tig * 2;

    float2 p00 = *(const float2*)(X + (size_t)r0 * DIM + c0);
    float2 p10 = *(const float2*)(X + (size_t)(r0 + 8) * DIM + c0);
    float2 p01 = *(const float2*)(X + (size_t)r0 * DIM + c0 + 8);
    float2 p11 = *(const float2*)(X + (size_t)(r0 + 8) * DIM + c0 + 8);

    uint32_t h[4], l[4];
    split_pair(p00.x, p00.y, h[0], l[0]);
    split_pair(p10.x, p10.y, h[1], l[1]);
    split_pair(p01.x, p01.y, h[2], l[2]);
    split_pair(p11.x, p11.y, h[3], l[3]);

    const size_t idx = (size_t)gw * 32 + lane;
    g_AFhi[idx] = make_uint4(h[0], h[1], h[2], h[3]);
    g_AFlo[idx] = make_uint4(l[0], l[1], l[2], l[3]);
}

// ============================================================================
// Kernel 0b: blocks [0,32): W -> B-fragments.
//            blocks [32,96): init g_s1/g_s2 (scalar, warp-computed, broadcast).
// ============================================================================
__global__ void __launch_bounds__(256)
convert_wfrag(const float* __restrict__ W, const float* __restrict__ bias,
              const float* __restrict__ a1, const float* __restrict__ a2,
              const float* __restrict__ att_b)
{
    if (blockIdx.x >= 32) {
        __shared__ float sc1, sc2;
        const int lane = threadIdx.x & 31;
        if (threadIdx.x < 32) {
            float d1 = 0.f, d2 = 0.f;
#pragma unroll
            for (int k = lane; k < DIM; k += 32) {
                float bv = __ldg(bias + k);
                d1 += bv * __ldg(a1 + k);
                d2 += bv * __ldg(a2 + k);
            }
#pragma unroll
            for (int o = 16; o; o >>= 1) {
                d1 += __shfl_xor_sync(0xffffffffu, d1, o);
                d2 += __shfl_xor_sync(0xffffffffu, d2, o);
            }
            if (lane == 0) { sc1 = d1 + att_b[0]; sc2 = d2; }
        }
        __syncthreads();
        const int row = (blockIdx.x - 32) * 256 + threadIdx.x;
        g_s1[row] = sc1;
        g_s2[row] = sc2;
        return;
    }

    const int gw   = blockIdx.x * 8 + (threadIdx.x >> 5);
    const int lane = threadIdx.x & 31;
    const int pair = gw >> 4;
    const int ks   = gw & 15;
    const int g   = lane >> 2;
    const int tig = lane & 3;
    const int n0 = pair * 16 + g;
    const int n1 = n0 + 8;
    const int k0 = ks * 16 + tig * 2;

    float2 q00 = *(const float2*)(W + (size_t)n0 * DIM + k0);
    float2 q01 = *(const float2*)(W + (size_t)n0 * DIM + k0 + 8);
    float2 q10 = *(const float2*)(W + (size_t)n1 * DIM + k0);
    float2 q11 = *(const float2*)(W + (size_t)n1 * DIM + k0 + 8);

    uint32_t h[4], l[4];
    split_pair(q00.x, q00.y, h[0], l[0]);
    split_pair(q01.x, q01.y, h[1], l[1]);
    split_pair(q10.x, q10.y, h[2], l[2]);
    split_pair(q11.x, q11.y, h[3], l[3]);

    const size_t idx = (size_t)gw * 32 + lane;
    g_BFhi[idx] = make_uint4(h[0], h[1], h[2], h[3]);
    g_BFlo[idx] = make_uint4(l[0], l[1], l[2], l[3]);
}

// ============================================================================
// Kernel 1: fragment-direct HMMA GEMM, CTA 64x128 (2 CTAs/SM, 512 CTAs),
// warp tile 32x32, fused s1/s2 epilogue, fp16 H output.
// ============================================================================
__global__ void __launch_bounds__(256, 2)
gemm_h_frag(const float* __restrict__ bias, const float* __restrict__ a1,
            const float* __restrict__ a2)
{
    const int tid  = threadIdx.x;
    const int wid  = tid >> 5;
    const int lane = tid & 31;
    const int cta_m = blockIdx.x * 64;
    const int cta_n = blockIdx.y * 128;

    const int wm = (wid & 1) * 32;    // 2 M positions
    const int wn = (wid >> 1) * 32;   // 4 N positions

    const int mt_base = (cta_m + wm) >> 4;   // 2 m16 tiles
    const int np_base = (cta_n + wn) >> 4;   // 2 n16 pairs

    const uint4* Ah = g_AFhi + (size_t)mt_base * 512 + lane;
    const uint4* Al = g_AFlo + (size_t)mt_base * 512 + lane;
    const uint4* Bh = g_BFhi + (size_t)np_base * 512 + lane;
    const uint4* Bl = g_BFlo + (size_t)np_base * 512 + lane;

    float acc[2][4][4];
#pragma unroll
    for (int mt = 0; mt < 2; mt++)
#pragma unroll
        for (int nt = 0; nt < 4; nt++)
#pragma unroll
            for (int c = 0; c < 4; c++) acc[mt][nt][c] = 0.f;

    uint4 cAh[2], cAl[2], cBh[2], cBl[2];
#pragma unroll
    for (int mt = 0; mt < 2; mt++) { cAh[mt] = Ah[mt * 512]; cAl[mt] = Al[mt * 512]; }
#pragma unroll
    for (int p = 0; p < 2; p++)    { cBh[p] = Bh[p * 512];   cBl[p] = Bl[p * 512]; }

#pragma unroll 1
    for (int ks = 0; ks < KSTEPS; ks++) {
        uint4 nAh[2], nAl[2], nBh[2], nBl[2];
        if (ks + 1 < KSTEPS) {
            const int o = (ks + 1) * 32;
#pragma unroll
            for (int mt = 0; mt < 2; mt++) {
                nAh[mt] = Ah[mt * 512 + o];
                nAl[mt] = Al[mt * 512 + o];
            }
#pragma unroll
            for (int p = 0; p < 2; p++) {
                nBh[p] = Bh[p * 512 + o];
                nBl[p] = Bl[p * 512 + o];
            }
        }

#pragma unroll
        for (int mt = 0; mt < 2; mt++) {
            const uint32_t* ah = (const uint32_t*)&cAh[mt];
            const uint32_t* al = (const uint32_t*)&cAl[mt];
#pragma unroll
            for (int nt = 0; nt < 4; nt++) {
                const uint32_t* qh = (const uint32_t*)&cBh[nt >> 1];
                const uint32_t* ql = (const uint32_t*)&cBl[nt >> 1];
                uint32_t bh[2] = { qh[(nt & 1) * 2], qh[(nt & 1) * 2 + 1] };
                uint32_t bl[2] = { ql[(nt & 1) * 2], ql[(nt & 1) * 2 + 1] };
                mma_bf16(acc[mt][nt], ah, bh);
                mma_bf16(acc[mt][nt], ah, bl);
                mma_bf16(acc[mt][nt], al, bh);
            }
        }

        if (ks + 1 < KSTEPS) {
#pragma unroll
            for (int mt = 0; mt < 2; mt++) { cAh[mt] = nAh[mt]; cAl[mt] = nAl[mt]; }
#pragma unroll
            for (int p = 0; p < 2; p++)    { cBh[p] = nBh[p];   cBl[p] = nBl[p]; }
        }
    }

    // ---- epilogue: +bias, fp16 H store, fused s1/s2 partials ----
    const int gid = lane >> 2;
    const int tig = lane & 3;

    float s1p[4], s2p[4];
#pragma unroll
    for (int e = 0; e < 4; e++) { s1p[e] = 0.f; s2p[e] = 0.f; }

#pragma unroll
    for (int nt = 0; nt < 4; nt++) {
        const int col = cta_n + wn + nt * 8 + tig * 2;
        const float2 bv  = *(const float2*)(bias + col);
        const float2 a1v = *(const float2*)(a1 + col);
        const float2 a2v = *(const float2*)(a2 + col);
#pragma unroll
        for (int mt = 0; mt < 2; mt++) {
            const int m0 = cta_m + wm + mt * 16 + gid;
            float2 v0 = make_float2(acc[mt][nt][0] + bv.x, acc[mt][nt][1] + bv.y);
            float2 v1 = make_float2(acc[mt][nt][2] + bv.x, acc[mt][nt][3] + bv.y);
            *(__half2*)(g_Hh + (size_t)m0 * DIM + col)       = __float22half2_rn(v0);
            *(__half2*)(g_Hh + (size_t)(m0 + 8) * DIM + col) = __float22half2_rn(v1);
            s1p[mt * 2 + 0] += acc[mt][nt][0] * a1v.x + acc[mt][nt][1] * a1v.y;
            s1p[mt * 2 + 1] += acc[mt][nt][2] * a1v.x + acc[mt][nt][3] * a1v.y;
            s2p[mt * 2 + 0] += acc[mt][nt][0] * a2v.x + acc[mt][nt][1] * a2v.y;
            s2p[mt * 2 + 1] += acc[mt][nt][2] * a2v.x + acc[mt][nt][3] * a2v.y;
        }
    }

#pragma unroll
    for (int e = 0; e < 4; e++) {
        s1p[e] += __shfl_xor_sync(0xffffffffu, s1p[e], 1);
        s1p[e] += __shfl_xor_sync(0xffffffffu, s1p[e], 2);
        s2p[e] += __shfl_xor_sync(0xffffffffu, s2p[e], 1);
        s2p[e] += __shfl_xor_sync(0xffffffffu, s2p[e], 2);
    }
    if (tig == 0) {
#pragma unroll
        for (int mt = 0; mt < 2; mt++) {
            const int m0 = cta_m + wm + mt * 16 + gid;
            atomicAdd(&g_s1[m0],     s1p[mt * 2 + 0]);
            atomicAdd(&g_s1[m0 + 8], s1p[mt * 2 + 1]);
            atomicAdd(&g_s2[m0],     s2p[mt * 2 + 0]);
            atomicAdd(&g_s2[m0 + 8], s2p[mt * 2 + 1]);
        }
    }
}

// ============================================================================
// Kernel 2: attention + aggregation — R15 structure (92.4us best);
// jbuf now stores j*DIM (kills the address IMAD in phase B).
// ============================================================================
__global__ void __launch_bounds__(256)
attn_agg_kernel(const float* __restrict__ adj, const float* __restrict__ mask,
                float* __restrict__ out)
{
    const int i   = blockIdx.x;
    const int b   = blockIdx.y;
    const int tid = threadIdx.x;
    const int row = b * NNODE + i;

    __shared__ float wbuf[NNODE];
    __shared__ int   jbuf[NNODE];
    __shared__ float sred[4][DIM];
    __shared__ int   s_cnt;
    __shared__ float s_sum;

    const float mi = mask[row];
    float* orow = out + (size_t)row * DIM;
    if (mi == 0.f) {
        orow[tid] = 0.f;
        return;
    }

    if (tid == 0) { s_cnt = 0; s_sum = 0.f; }
    __syncthreads();

    const float* arow = adj + (size_t)row * NNODE;
    const float* mrow = mask + b * NNODE;
    const float* s2b  = g_s2 + b * NNODE;
    const float  s1i  = g_s1[row];
    const int lane = tid & 31;

    // ---- Phase A: flags + single prefix-sum compaction ----
    float4 av[2], mv[2];
#pragma unroll
    for (int u = 0; u < 2; u++) {
        int j0 = tid * 4 + u * 1024;
        av[u] = *(const float4*)(arow + j0);
        mv[u] = *(const float4*)(mrow + j0);
    }

    unsigned flags = 0;
#pragma unroll
    for (int u = 0; u < 2; u++) {
        const float* ap = (const float*)&av[u];
        const float* mp = (const float*)&mv[u];
#pragma unroll
        for (int e = 0; e < 4; e++)
            if (ap[e] * mp[e] != 0.f) flags |= 1u << (u * 4 + e);
    }

    const int cnt = __popc(flags);
    int inc = cnt;
#pragma unroll
    for (int o = 1; o < 32; o <<= 1) {
        int v = __shfl_up_sync(0xffffffffu, inc, o);
        if (lane >= o) inc += v;
    }
    const int wtot = __shfl_sync(0xffffffffu, inc, 31);
    int base = 0;
    if (lane == 31) base = atomicAdd(&s_cnt, wtot);
    base = __shfl_sync(0xffffffffu, base, 31);

    int pos = base + inc - cnt;
    unsigned f = flags;
    while (f) {
        int e = __ffs(f) - 1;
        f &= f - 1;
        jbuf[pos++] = tid * 4 + (e >> 2) * 1024 + (e & 3);
    }
    __syncthreads();

    // ---- Phase A2: sigmoid on compacted entries; pre-scale j by DIM ----
    const int n = s_cnt;
    float psum = 0.f;
    for (int t = tid; t < n; t += 256) {
        int j = jbuf[t];
        float lg = s1i + s2b[j];
        float w = __fdividef(1.f, 1.f + __expf(-lg));
        wbuf[t] = w;
        jbuf[t] = j << 8;                 // j * DIM
        psum += w;
    }
#pragma unroll
    for (int o = 16; o; o >>= 1) psum += __shfl_xor_sync(0xffffffffu, psum, o);
    if (lane == 0 && psum != 0.f) atomicAdd(&s_sum, psum);
    __syncthreads();

    // ---- Phase B: gather fp16 H (uint2 per thread per neighbor) ----
    const float inv = 1.f / (s_sum + 1e-8f);
    const __half* Hb = g_Hh + (size_t)b * NNODE * DIM;

    const int g  = tid >> 6;
    const int c4 = (tid & 63) * 4;

    float4 acc = make_float4(0.f, 0.f, 0.f, 0.f);
    int k = g;
    for (; k + 4 < n; k += 8) {
        int   ja = jbuf[k],   jc = jbuf[k + 4];
        float wa = wbuf[k],   wc = wbuf[k + 4];
        uint2 ra = *(const uint2*)(Hb + ja + c4);
        uint2 rc = *(const uint2*)(Hb + jc + c4);
        float2 a0 = __half22float2(*(__half2*)&ra.x);
        float2 a1f = __half22float2(*(__half2*)&ra.y);
        float2 c0 = __half22float2(*(__half2*)&rc.x);
        float2 c1 = __half22float2(*(__half2*)&rc.y);
        acc.x += wa * a0.x  + wc * c0.x;
        acc.y += wa * a0.y  + wc * c0.y;
        acc.z += wa * a1f.x + wc * c1.x;
        acc.w += wa * a1f.y + wc * c1.y;
    }
    if (k < n) {
        int   ja = jbuf[k];
        float wa = wbuf[k];
        uint2 ra = *(const uint2*)(Hb + ja + c4);
        float2 a0 = __half22float2(*(__half2*)&ra.x);
        float2 a1f = __half22float2(*(__half2*)&ra.y);
        acc.x += wa * a0.x;  acc.y += wa * a0.y;
        acc.z += wa * a1f.x; acc.w += wa * a1f.y;
    }

    *(float4*)&sred[g][c4] = acc;
    __syncthreads();

    float r = sred[0][tid] + sred[1][tid] + sred[2][tid] + sred[3][tid];
    orow[tid] = r * inv;
}

// ============================================================================
// Launch: cx(0), cw+init(1), gemm(2), attn(3)
// ============================================================================
extern "C" void kernel_launch(void* const* d_in, const int* in_sizes, int n_in,
                              void* d_out, int out_size)
{
    const float* x     = (const float*)d_in[0];
    const float* adj   = (const float*)d_in[1];
    const float* mask  = (const float*)d_in[2];
    const float* W     = (const float*)d_in[3];
    const float* bias  = (const float*)d_in[4];
    const float* a1    = (const float*)d_in[5];
    const float* a2    = (const float*)d_in[6];
    const float* att_b = (const float*)d_in[7];
    float* out = (float*)d_out;

    convert_xfrag<<<(MTILES * KSTEPS) / 8, 256>>>(x);
    convert_wfrag<<<96, 256>>>(W, bias, a1, a2, att_b);

    dim3 g1(MROWS / 64, DIM / 128);       // (256, 2) = 512 CTAs
    gemm_h_frag<<<g1, 256>>>(bias, a1, a2);

    dim3 g3(NNODE, BATCH);                // (2048, 8)
    attn_agg_kernel<<<g3, 256>>>(adj, mask, out);
}